// round 3
// baseline (speedup 1.0000x reference)
#include <cuda_runtime.h>
#include <cuda_bf16.h>
#include <cstdint>

// ---------------- Problem constants (dataset-fixed) ----------------
#define DIMK   1024            // hidden dim per direction
#define VOCABN 32000           // vocab
#define MP     3712            // padded packed-row count, 29 tiles of 128
#define NCH    (VOCABN / 128)  // 250 vocab chunks of 128
#define KCH    (DIMK / 64)     // 16 K-chunks of 64 bf16
#define L2E    1.4426950408889634f
#define LN2    0.6931471805599453f

// ---------------- Scratch (static device globals; no allocs) ----------------
__device__ __nv_bfloat16 g_A[(size_t)MP * DIMK];        // gathered ctx rows, bf16
__device__ __nv_bfloat16 g_W[(size_t)VOCABN * DIMK];    // weight, bf16
__device__ float2        g_part[(size_t)MP * NCH];      // per (row, chunk): {max, sumexp}
__device__ float         g_lse[MP];
__device__ float         g_gold[MP];
__device__ int           g_ctx[MP];
__device__ int           g_tok[MP];
__device__ int           g_hdr[4];                      // Nf, Nb, M
__device__ float         g_denom;

// ---------------- PTX helpers (base ISA only: cp.async / ldmatrix / mma.sync) ----
__device__ __forceinline__ uint32_t smem_u32(const void* p) {
    uint32_t a;
    asm("{ .reg .u64 t; cvta.to.shared.u64 t, %1; cvt.u32.u64 %0, t; }" : "=r"(a) : "l"(p));
    return a;
}
__device__ __forceinline__ void cp_async16(uint32_t saddr, const void* gaddr) {
    asm volatile("cp.async.cg.shared.global [%0], [%1], 16;" :: "r"(saddr), "l"(gaddr));
}
__device__ __forceinline__ void cp_commit() { asm volatile("cp.async.commit_group;" ::: "memory"); }
__device__ __forceinline__ void cp_wait1()  { asm volatile("cp.async.wait_group 1;" ::: "memory"); }

__device__ __forceinline__ void ldmatrix_x4(uint32_t& r0, uint32_t& r1, uint32_t& r2, uint32_t& r3,
                                            uint32_t addr) {
    asm volatile("ldmatrix.sync.aligned.m8n8.x4.shared.b16 {%0,%1,%2,%3}, [%4];"
                 : "=r"(r0), "=r"(r1), "=r"(r2), "=r"(r3) : "r"(addr));
}
__device__ __forceinline__ void mma16816(float* c,
                                         uint32_t a0, uint32_t a1, uint32_t a2, uint32_t a3,
                                         uint32_t b0, uint32_t b1) {
    asm volatile(
        "mma.sync.aligned.m16n8k16.row.col.f32.bf16.bf16.f32 "
        "{%0,%1,%2,%3}, {%4,%5,%6,%7}, {%8,%9}, {%0,%1,%2,%3};"
        : "+f"(c[0]), "+f"(c[1]), "+f"(c[2]), "+f"(c[3])
        : "r"(a0), "r"(a1), "r"(a2), "r"(a3), "r"(b0), "r"(b1));
}

// online-softmax pair combine
__device__ __forceinline__ void lse_combine(float& m, float& s, float m2, float s2) {
    float mx = fmaxf(m, m2);
    s = s * exp2f((m - mx) * L2E) + s2 * exp2f((m2 - mx) * L2E);
    m = mx;
}

// ---------------- K1: index build (device-side, bs only known on device) ----------------
__global__ void k_build(const int* __restrict__ bs, const int* __restrict__ sent, int T, int total) {
    __shared__ int off[257];
    int tid = threadIdx.x;
    if (tid == 0) {
        int acc = 0;
        for (int t = 0; t < T; ++t) { off[t] = acc; acc += bs[t]; }
        off[T] = acc;
    }
    __syncthreads();
    int rb = 0;
    for (int t = 1; t < T; ++t) {              // forward: h[t-1] predicts tok[t]
        int n = bs[t];
        for (int j = tid; j < n; j += blockDim.x) {
            g_ctx[rb + j] = off[t - 1] + j;
            g_tok[rb + j] = sent[off[t] + j];
        }
        rb += n;
    }
    int Nf = rb;
    for (int i = 1; i < T - 1; ++i) {          // backward: h[i+1] predicts tok[i]
        int n = bs[i + 1];
        for (int j = tid; j < n; j += blockDim.x) {
            g_ctx[rb + j] = off[i + 1] + j;
            g_tok[rb + j] = sent[off[i] + j];
        }
        rb += n;
    }
    int M = rb;
    for (int r = M + tid; r < MP; r += blockDim.x) { g_ctx[r] = 0; g_tok[r] = 0; }
    if (tid == 0) {
        g_hdr[0] = Nf; g_hdr[1] = M - Nf; g_hdr[2] = M;
        g_denom = (float)(2 * total - bs[0] - bs[T - 1]);
    }
}

// ---------------- K2: gather ctx rows -> bf16 A (zero pad rows) ----------------
__global__ void k_gather(const float* __restrict__ hid) {
    int row = blockIdx.x, tid = threadIdx.x;
    int M = g_hdr[2], Nf = g_hdr[0];
    uint2* dst = reinterpret_cast<uint2*>(&g_A[(size_t)row * DIMK]);
    if (row < M) {
        int src = g_ctx[row];
        const float4* p = reinterpret_cast<const float4*>(
            hid + (size_t)src * 2 * DIMK + (row < Nf ? 0 : DIMK));
        float4 v = p[tid];
        __nv_bfloat162 lo = __floats2bfloat162_rn(v.x, v.y);
        __nv_bfloat162 hi = __floats2bfloat162_rn(v.z, v.w);
        uint2 o;
        o.x = *reinterpret_cast<uint32_t*>(&lo);
        o.y = *reinterpret_cast<uint32_t*>(&hi);
        dst[tid] = o;
    } else {
        dst[tid] = make_uint2(0u, 0u);
    }
}

// ---------------- K3: weight fp32 -> bf16 ----------------
__global__ void k_wconv(const float* __restrict__ W) {
    const int n4 = VOCABN * DIMK / 4;
    for (int i = blockIdx.x * blockDim.x + threadIdx.x; i < n4; i += gridDim.x * blockDim.x) {
        float4 v = reinterpret_cast<const float4*>(W)[i];
        __nv_bfloat162 lo = __floats2bfloat162_rn(v.x, v.y);
        __nv_bfloat162 hi = __floats2bfloat162_rn(v.z, v.w);
        uint2 o;
        o.x = *reinterpret_cast<uint32_t*>(&lo);
        o.y = *reinterpret_cast<uint32_t*>(&hi);
        reinterpret_cast<uint2*>(g_W)[i] = o;
    }
}

// ---------------- K4: mma.sync GEMM + fused online max/sumexp epilogue ----------------
// grid = (NCH, MP/128), 256 threads (8 warps). CTA tile 128(M) x 128(N) x 64(K).
// Warp w owns rows [w*16, w*16+16) across all 128 N cols -> per-row reduce stays in-warp.
#define GEMM_SMEM 67584
__global__ __launch_bounds__(256)
void k_gemm(const float* __restrict__ fbias, const float* __restrict__ bbias) {
    extern __shared__ char dynsmem[];
    uint32_t raw = smem_u32(dynsmem);
    uint32_t pad = (1024u - (raw & 1023u)) & 1023u;
    uint32_t sb  = raw + pad;
    char* base   = dynsmem + pad;

    const uint32_t sA[2] = { sb,         sb + 16384 };
    const uint32_t sB[2] = { sb + 32768, sb + 49152 };
    float* biasF = reinterpret_cast<float*>(base + 65536);
    float* biasB = biasF + 128;

    int tid  = threadIdx.x;
    int warp = tid >> 5;
    int lane = tid & 31;
    int nb = blockIdx.x, mb = blockIdx.y;
    int n0 = nb * 128, m0 = mb * 128;

    if (tid < 128) biasF[tid] = fbias[n0 + tid];
    else           biasB[tid - 128] = bbias[n0 + tid - 128];

    const __nv_bfloat16* Ag = g_A + (size_t)m0 * DIMK;
    const __nv_bfloat16* Bg = g_W + (size_t)n0 * DIMK;

    // tile loader: 128 rows x 64 bf16 (128B/row) with SW128-style swizzle, 16B cp.async
    auto load_tile = [&](uint32_t sdst, const __nv_bfloat16* src, int k0) {
        #pragma unroll
        for (int i = 0; i < 4; ++i) {
            int idx = tid + i * 256;
            int r = idx >> 3, c = idx & 7;
            uint32_t off = (uint32_t)(r * 128 + c * 16);
            uint32_t sw  = off ^ ((off >> 3) & 0x70u);
            cp_async16(sdst + sw, src + (size_t)r * DIMK + k0 + c * 8);
        }
    };

    load_tile(sA[0], Ag, 0);  load_tile(sB[0], Bg, 0);  cp_commit();
    load_tile(sA[1], Ag, 64); load_tile(sB[1], Bg, 64); cp_commit();

    float c[16][4];
    #pragma unroll
    for (int j = 0; j < 16; ++j)
        #pragma unroll
        for (int q = 0; q < 4; ++q) c[j][q] = 0.f;

    // precomputed fragment addresses (constant across chunks except kstep col)
    const uint32_t a_row = (uint32_t)(warp * 16 + (lane & 15));
    const uint32_t a_kh  = (uint32_t)((lane >> 4) << 3);          // 0 or 8
    const uint32_t b_r8  = (uint32_t)((lane & 7) + ((lane >> 4) << 3));  // row-in-16 block
    const uint32_t b_kh  = (uint32_t)(((lane >> 3) & 1) << 3);    // 0 or 8

    for (int kc = 0; kc < KCH; ++kc) {
        int buf = kc & 1;
        cp_wait1();
        __syncthreads();
        uint32_t abase = sA[buf], bbase = sB[buf];
        #pragma unroll
        for (int s = 0; s < 4; ++s) {
            uint32_t a0, a1, a2, a3;
            {
                uint32_t off = a_row * 128u + (uint32_t)(s * 16) * 2u + a_kh * 2u;
                off ^= (off >> 3) & 0x70u;
                ldmatrix_x4(a0, a1, a2, a3, abase + off);
            }
            #pragma unroll
            for (int p = 0; p < 8; ++p) {
                uint32_t b0, b1, b2, b3;
                uint32_t nrow = (uint32_t)(p * 16) + b_r8;
                uint32_t off  = nrow * 128u + (uint32_t)(s * 16) * 2u + b_kh * 2u;
                off ^= (off >> 3) & 0x70u;
                ldmatrix_x4(b0, b1, b2, b3, bbase + off);
                mma16816(c[2 * p],     a0, a1, a2, a3, b0, b1);
                mma16816(c[2 * p + 1], a0, a1, a2, a3, b2, b3);
            }
        }
        __syncthreads();
        int kn = kc + 2;
        if (kn < KCH) { load_tile(sA[buf], Ag, kn * 64); load_tile(sB[buf], Bg, kn * 64); }
        cp_commit();
    }

    // ----- epilogue: per-row online max/sumexp over 128 cols, in-warp -----
    int rA = warp * 16 + (lane >> 2);       // local row for c[j][0..1]
    int rB = rA + 8;                        // local row for c[j][2..3]
    int Nf = g_hdr[0];
    int gA = m0 + rA, gB = m0 + rB;
    const float* biasRowA = (gA < Nf) ? biasF : biasB;
    const float* biasRowB = (gB < Nf) ? biasF : biasB;
    int cbase = (lane & 3) * 2;

    float mA = -3.4e38f, sAcc = 0.f, mB = -3.4e38f, sBcc = 0.f;
    #pragma unroll
    for (int j = 0; j < 16; ++j) {
        int col = j * 8 + cbase;
        float vA0 = c[j][0] + biasRowA[col];
        float vA1 = c[j][1] + biasRowA[col + 1];
        float vB0 = c[j][2] + biasRowB[col];
        float vB1 = c[j][3] + biasRowB[col + 1];
        // row A
        float mx = fmaxf(vA0, vA1);
        if (mx > mA) { sAcc = sAcc * exp2f((mA - mx) * L2E); mA = mx; }
        sAcc += exp2f((vA0 - mA) * L2E) + exp2f((vA1 - mA) * L2E);
        // row B
        mx = fmaxf(vB0, vB1);
        if (mx > mB) { sBcc = sBcc * exp2f((mB - mx) * L2E); mB = mx; }
        sBcc += exp2f((vB0 - mB) * L2E) + exp2f((vB1 - mB) * L2E);
    }
    // quad reduce (lanes differing in bits 0,1 share the same row)
    #pragma unroll
    for (int d = 1; d <= 2; d <<= 1) {
        float m2 = __shfl_xor_sync(0xffffffffu, mA, d);
        float s2 = __shfl_xor_sync(0xffffffffu, sAcc, d);
        lse_combine(mA, sAcc, m2, s2);
        m2 = __shfl_xor_sync(0xffffffffu, mB, d);
        s2 = __shfl_xor_sync(0xffffffffu, sBcc, d);
        lse_combine(mB, sBcc, m2, s2);
    }
    if ((lane & 3) == 0) {
        g_part[(size_t)gA * NCH + nb] = make_float2(mA, sAcc);
        g_part[(size_t)gB * NCH + nb] = make_float2(mB, sBcc);
    }
}

// ---------------- K5: per-row lse reduce over 250 partials ----------------
__global__ void k_lse() {
    __shared__ float red[256];
    int row = blockIdx.x, tid = threadIdx.x;
    float2 p = (tid < NCH) ? g_part[(size_t)row * NCH + tid] : make_float2(-3.4e38f, 0.f);
    red[tid] = p.x; __syncthreads();
    for (int s = 128; s > 0; s >>= 1) {
        if (tid < s) red[tid] = fmaxf(red[tid], red[tid + s]);
        __syncthreads();
    }
    float gmax = red[0]; __syncthreads();
    red[tid] = p.y * exp2f((p.x - gmax) * L2E);
    __syncthreads();
    for (int s = 128; s > 0; s >>= 1) {
        if (tid < s) red[tid] += red[tid + s];
        __syncthreads();
    }
    if (tid == 0) g_lse[row] = gmax + LN2 * log2f(red[0]);
}

// ---------------- K6: exact fp32 gold logit per row ----------------
__global__ void k_gold(const float* __restrict__ hid, const float* __restrict__ W,
                       const float* __restrict__ fb, const float* __restrict__ bb) {
    __shared__ float red[256];
    int row = blockIdx.x, tid = threadIdx.x;
    int M = g_hdr[2], Nf = g_hdr[0];
    if (row >= M) return;
    int src = g_ctx[row], tok = g_tok[row];
    const float4* h4 = reinterpret_cast<const float4*>(
        hid + (size_t)src * 2 * DIMK + (row < Nf ? 0 : DIMK));
    const float4* w4 = reinterpret_cast<const float4*>(W + (size_t)tok * DIMK);
    float4 a = h4[tid], b = w4[tid];
    red[tid] = a.x * b.x + a.y * b.y + a.z * b.z + a.w * b.w;
    __syncthreads();
    for (int s = 128; s > 0; s >>= 1) {
        if (tid < s) red[tid] += red[tid + s];
        __syncthreads();
    }
    if (tid == 0) g_gold[row] = red[0] + (row < Nf ? fb[tok] : bb[tok]);
}

// ---------------- K7: final scalar ----------------
__global__ void k_final(float* __restrict__ out) {
    __shared__ float red[1024];
    int tid = threadIdx.x, M = g_hdr[2];
    float a = 0.f;
    for (int r = tid; r < M; r += 1024) a += g_lse[r] - g_gold[r];
    red[tid] = a; __syncthreads();
    for (int s = 512; s > 0; s >>= 1) {
        if (tid < s) red[tid] += red[tid + s];
        __syncthreads();
    }
    if (tid == 0) out[0] = red[0] / g_denom;
}

// ---------------- launch ----------------
extern "C" void kernel_launch(void* const* d_in, const int* in_sizes, int n_in,
                              void* d_out, int out_size) {
    const float* hid  = (const float*)d_in[0];
    const float* W    = (const float*)d_in[1];
    const float* fb   = (const float*)d_in[2];
    const float* bb   = (const float*)d_in[3];
    const int*   sent = (const int*)d_in[4];
    const int*   bs   = (const int*)d_in[5];
    int total = in_sizes[4];
    int T     = in_sizes[5];

    cudaFuncSetAttribute(k_gemm, cudaFuncAttributeMaxDynamicSharedMemorySize, GEMM_SMEM);

    k_build<<<1, 256>>>(bs, sent, T, total);
    k_gather<<<MP, 256>>>(hid);
    k_wconv<<<4096, 256>>>(W);
    k_gemm<<<dim3(NCH, MP / 128), 256, GEMM_SMEM>>>(fb, bb);
    k_lse<<<MP, 256>>>();
    k_gold<<<MP, 256>>>(hid, W, fb, bb);
    k_final<<<1, 1024>>>((float*)d_out);
}

// round 4
// speedup vs baseline: 1.0762x; 1.0762x over previous
#include <cuda_runtime.h>
#include <cuda_bf16.h>
#include <cstdint>

// ---------------- Problem constants (dataset-fixed) ----------------
#define DIMK   1024            // hidden dim per direction
#define VOCABN 32000           // vocab
#define MP     3712            // padded packed-row count, 29 tiles of 128
#define NCH    (VOCABN / 128)  // 250 vocab chunks of 128
#define KCH    (DIMK / 64)     // 16 K-chunks of 64 bf16
#define L2E    1.4426950408889634f
#define LN2    0.6931471805599453f

// ---------------- Scratch (static device globals; no allocs) ----------------
__device__ __nv_bfloat16 g_A[(size_t)MP * DIMK];        // gathered ctx rows, bf16
__device__ __nv_bfloat16 g_W[(size_t)VOCABN * DIMK];    // weight, bf16
__device__ float2        g_part[(size_t)MP * NCH];      // per (row, chunk): {max, sumexp}
__device__ float         g_lse[MP];
__device__ float         g_gold[MP];
__device__ int           g_ctx[MP];
__device__ int           g_tok[MP];
__device__ int           g_hdr[4];                      // Nf, Nb, M
__device__ float         g_denom;

// ---------------- PTX helpers (base ISA: cp.async / ldmatrix / mma.sync) ----
__device__ __forceinline__ uint32_t smem_u32(const void* p) {
    uint32_t a;
    asm("{ .reg .u64 t; cvta.to.shared.u64 t, %1; cvt.u32.u64 %0, t; }" : "=r"(a) : "l"(p));
    return a;
}
__device__ __forceinline__ void cp_async16(uint32_t saddr, const void* gaddr) {
    asm volatile("cp.async.cg.shared.global [%0], [%1], 16;" :: "r"(saddr), "l"(gaddr));
}
__device__ __forceinline__ void cp_commit() { asm volatile("cp.async.commit_group;" ::: "memory"); }
__device__ __forceinline__ void cp_wait1()  { asm volatile("cp.async.wait_group 1;" ::: "memory"); }

__device__ __forceinline__ void ldmatrix_x4(uint32_t& r0, uint32_t& r1, uint32_t& r2, uint32_t& r3,
                                            uint32_t addr) {
    asm volatile("ldmatrix.sync.aligned.m8n8.x4.shared.b16 {%0,%1,%2,%3}, [%4];"
                 : "=r"(r0), "=r"(r1), "=r"(r2), "=r"(r3) : "r"(addr));
}
__device__ __forceinline__ void mma16816(float* c,
                                         uint32_t a0, uint32_t a1, uint32_t a2, uint32_t a3,
                                         uint32_t b0, uint32_t b1) {
    asm volatile(
        "mma.sync.aligned.m16n8k16.row.col.f32.bf16.bf16.f32 "
        "{%0,%1,%2,%3}, {%4,%5,%6,%7}, {%8,%9}, {%0,%1,%2,%3};"
        : "+f"(c[0]), "+f"(c[1]), "+f"(c[2]), "+f"(c[3])
        : "r"(a0), "r"(a1), "r"(a2), "r"(a3), "r"(b0), "r"(b1));
}

// online-softmax pair combine
__device__ __forceinline__ void lse_combine(float& m, float& s, float m2, float s2) {
    float mx = fmaxf(m, m2);
    s = s * exp2f((m - mx) * L2E) + s2 * exp2f((m2 - mx) * L2E);
    m = mx;
}

// ---------------- K1: index build ----------------
__global__ void k_build(const int* __restrict__ bs, const int* __restrict__ sent, int T, int total) {
    __shared__ int off[257];
    int tid = threadIdx.x;
    if (tid == 0) {
        int acc = 0;
        for (int t = 0; t < T; ++t) { off[t] = acc; acc += bs[t]; }
        off[T] = acc;
    }
    __syncthreads();
    int rb = 0;
    for (int t = 1; t < T; ++t) {              // forward: h[t-1] predicts tok[t]
        int n = bs[t];
        for (int j = tid; j < n; j += blockDim.x) {
            g_ctx[rb + j] = off[t - 1] + j;
            g_tok[rb + j] = sent[off[t] + j];
        }
        rb += n;
    }
    int Nf = rb;
    for (int i = 1; i < T - 1; ++i) {          // backward: h[i+1] predicts tok[i]
        int n = bs[i + 1];
        for (int j = tid; j < n; j += blockDim.x) {
            g_ctx[rb + j] = off[i + 1] + j;
            g_tok[rb + j] = sent[off[i] + j];
        }
        rb += n;
    }
    int M = rb;
    for (int r = M + tid; r < MP; r += blockDim.x) { g_ctx[r] = 0; g_tok[r] = 0; }
    if (tid == 0) {
        g_hdr[0] = Nf; g_hdr[1] = M - Nf; g_hdr[2] = M;
        g_denom = (float)(2 * total - bs[0] - bs[T - 1]);
    }
}

// ---------------- K2: gather ctx rows -> bf16 A (zero pad rows) ----------------
__global__ void k_gather(const float* __restrict__ hid) {
    int row = blockIdx.x, tid = threadIdx.x;
    int M = g_hdr[2], Nf = g_hdr[0];
    uint2* dst = reinterpret_cast<uint2*>(&g_A[(size_t)row * DIMK]);
    if (row < M) {
        int src = g_ctx[row];
        const float4* p = reinterpret_cast<const float4*>(
            hid + (size_t)src * 2 * DIMK + (row < Nf ? 0 : DIMK));
        float4 v = p[tid];
        __nv_bfloat162 lo = __floats2bfloat162_rn(v.x, v.y);
        __nv_bfloat162 hi = __floats2bfloat162_rn(v.z, v.w);
        uint2 o;
        o.x = *reinterpret_cast<uint32_t*>(&lo);
        o.y = *reinterpret_cast<uint32_t*>(&hi);
        dst[tid] = o;
    } else {
        dst[tid] = make_uint2(0u, 0u);
    }
}

// ---------------- K3: weight fp32 -> bf16 ----------------
__global__ void k_wconv(const float* __restrict__ W) {
    const int n4 = VOCABN * DIMK / 4;
    for (int i = blockIdx.x * blockDim.x + threadIdx.x; i < n4; i += gridDim.x * blockDim.x) {
        float4 v = reinterpret_cast<const float4*>(W)[i];
        __nv_bfloat162 lo = __floats2bfloat162_rn(v.x, v.y);
        __nv_bfloat162 hi = __floats2bfloat162_rn(v.z, v.w);
        uint2 o;
        o.x = *reinterpret_cast<uint32_t*>(&lo);
        o.y = *reinterpret_cast<uint32_t*>(&hi);
        reinterpret_cast<uint2*>(g_W)[i] = o;
    }
}

// ---------------- K4: mma.sync GEMM + fused online max/sumexp epilogue ----------------
// grid = (NCH, MP/128), 256 threads (8 warps as 4(M) x 2(N)).
// CTA tile 128(M) x 128(N) x 64(K); warp tile 32(M) x 64(N).
#define GEMM_SMEM 69632
__global__ __launch_bounds__(256, 2)
void k_gemm(const float* __restrict__ fbias, const float* __restrict__ bbias) {
    extern __shared__ char dynsmem[];
    uint32_t raw = smem_u32(dynsmem);
    uint32_t pad = (1024u - (raw & 1023u)) & 1023u;
    uint32_t sb  = raw + pad;
    char* base   = dynsmem + pad;

    const uint32_t sA[2] = { sb,         sb + 16384 };
    const uint32_t sB[2] = { sb + 32768, sb + 49152 };
    float*  biasF = reinterpret_cast<float*>(base + 65536);          // 128 f
    float*  biasB = biasF + 128;                                     // 128 f
    float2* scr   = reinterpret_cast<float2*>(base + 66560);         // [128][2]

    int tid  = threadIdx.x;
    int warp = tid >> 5;
    int lane = tid & 31;
    int wm   = warp >> 1;        // 0..3  (M strip of 32)
    int wn   = warp & 1;         // 0..1  (N strip of 64)
    int nb = blockIdx.x, mb = blockIdx.y;
    int n0 = nb * 128, m0 = mb * 128;

    if (tid < 128) biasF[tid] = fbias[n0 + tid];
    else           biasB[tid - 128] = bbias[n0 + tid - 128];

    const __nv_bfloat16* Ag = g_A + (size_t)m0 * DIMK;
    const __nv_bfloat16* Bg = g_W + (size_t)n0 * DIMK;

    // tile loader: 128 rows x 64 bf16 (128B/row), SW128-style swizzle, 16B cp.async
    auto load_tile = [&](uint32_t sdst, const __nv_bfloat16* src, int k0) {
        #pragma unroll
        for (int i = 0; i < 4; ++i) {
            int idx = tid + i * 256;
            int r = idx >> 3, c = idx & 7;
            uint32_t off = (uint32_t)(r * 128 + c * 16);
            uint32_t sw  = off ^ ((off >> 3) & 0x70u);
            cp_async16(sdst + sw, src + (size_t)r * DIMK + k0 + c * 8);
        }
    };

    load_tile(sA[0], Ag, 0);  load_tile(sB[0], Bg, 0);  cp_commit();
    load_tile(sA[1], Ag, 64); load_tile(sB[1], Bg, 64); cp_commit();

    float c[2][8][4];
    #pragma unroll
    for (int mi = 0; mi < 2; ++mi)
        #pragma unroll
        for (int nj = 0; nj < 8; ++nj)
            #pragma unroll
            for (int q = 0; q < 4; ++q) c[mi][nj][q] = 0.f;

    // fragment row/col components (constant across chunks)
    const uint32_t a_row = (uint32_t)(wm * 32 + (lane & 15));        // + mi*16
    const uint32_t a_kb  = (uint32_t)((lane >> 4) << 4);             // 0 or 16 bytes
    const uint32_t b_row = (uint32_t)(wn * 64 + (lane & 7) + ((lane >> 4) << 3)); // + nj2*16
    const uint32_t b_kb  = (uint32_t)(((lane >> 3) & 1) << 4);       // 0 or 16 bytes

    for (int kc = 0; kc < KCH; ++kc) {
        int buf = kc & 1;
        cp_wait1();
        __syncthreads();
        uint32_t abase = sA[buf], bbase = sB[buf];
        #pragma unroll
        for (int s = 0; s < 4; ++s) {
            uint32_t a[2][4];
            #pragma unroll
            for (int mi = 0; mi < 2; ++mi) {
                uint32_t off = (a_row + mi * 16) * 128u + (uint32_t)(s * 32) + a_kb;
                off ^= (off >> 3) & 0x70u;
                ldmatrix_x4(a[mi][0], a[mi][1], a[mi][2], a[mi][3], abase + off);
            }
            #pragma unroll
            for (int nj2 = 0; nj2 < 4; ++nj2) {
                uint32_t b0, b1, b2, b3;
                uint32_t off = (b_row + nj2 * 16) * 128u + (uint32_t)(s * 32) + b_kb;
                off ^= (off >> 3) & 0x70u;
                ldmatrix_x4(b0, b1, b2, b3, bbase + off);
                #pragma unroll
                for (int mi = 0; mi < 2; ++mi) {
                    mma16816(c[mi][2 * nj2],     a[mi][0], a[mi][1], a[mi][2], a[mi][3], b0, b1);
                    mma16816(c[mi][2 * nj2 + 1], a[mi][0], a[mi][1], a[mi][2], a[mi][3], b2, b3);
                }
            }
        }
        __syncthreads();
        int kn = kc + 2;
        if (kn < KCH) { load_tile(sA[buf], Ag, kn * 64); load_tile(sB[buf], Bg, kn * 64); }
        cp_commit();
    }

    // ----- epilogue: per-row online max/sumexp over this warp's 64 cols -----
    int Nf = g_hdr[0];
    int cb = wn * 64 + (lane & 3) * 2;      // local col of c[.][nj][0]
    float mv[2][2], sv[2][2];
    const float* bp[2][2];
    int lrow[2][2];
    #pragma unroll
    for (int mi = 0; mi < 2; ++mi)
        #pragma unroll
        for (int h = 0; h < 2; ++h) {
            lrow[mi][h] = wm * 32 + mi * 16 + h * 8 + (lane >> 2);
            bp[mi][h]   = (m0 + lrow[mi][h] < Nf) ? biasF : biasB;
            mv[mi][h]   = -3.4e38f;
            sv[mi][h]   = 0.f;
        }
    #pragma unroll
    for (int nj = 0; nj < 8; ++nj) {
        int col = cb + nj * 8;
        #pragma unroll
        for (int mi = 0; mi < 2; ++mi) {
            float v0 = c[mi][nj][0] + bp[mi][0][col];
            float v1 = c[mi][nj][1] + bp[mi][0][col + 1];
            float mx = fmaxf(v0, v1);
            if (mx > mv[mi][0]) { sv[mi][0] *= exp2f((mv[mi][0] - mx) * L2E); mv[mi][0] = mx; }
            sv[mi][0] += exp2f((v0 - mv[mi][0]) * L2E) + exp2f((v1 - mv[mi][0]) * L2E);

            float w0 = c[mi][nj][2] + bp[mi][1][col];
            float w1 = c[mi][nj][3] + bp[mi][1][col + 1];
            mx = fmaxf(w0, w1);
            if (mx > mv[mi][1]) { sv[mi][1] *= exp2f((mv[mi][1] - mx) * L2E); mv[mi][1] = mx; }
            sv[mi][1] += exp2f((w0 - mv[mi][1]) * L2E) + exp2f((w1 - mv[mi][1]) * L2E);
        }
    }
    // quad reduce (lanes differing in bits 0,1 share each row)
    #pragma unroll
    for (int mi = 0; mi < 2; ++mi)
        #pragma unroll
        for (int h = 0; h < 2; ++h)
            #pragma unroll
            for (int d = 1; d <= 2; d <<= 1) {
                float m2 = __shfl_xor_sync(0xffffffffu, mv[mi][h], d);
                float s2 = __shfl_xor_sync(0xffffffffu, sv[mi][h], d);
                lse_combine(mv[mi][h], sv[mi][h], m2, s2);
            }
    if ((lane & 3) == 0) {
        #pragma unroll
        for (int mi = 0; mi < 2; ++mi)
            #pragma unroll
            for (int h = 0; h < 2; ++h)
                scr[lrow[mi][h] * 2 + wn] = make_float2(mv[mi][h], sv[mi][h]);
    }
    __syncthreads();
    if (tid < 128) {
        float2 p0 = scr[tid * 2 + 0], p1 = scr[tid * 2 + 1];
        lse_combine(p0.x, p0.y, p1.x, p1.y);
        g_part[(size_t)(m0 + tid) * NCH + nb] = p0;
    }
}

// ---------------- K5: per-row lse reduce over 250 partials ----------------
__global__ void k_lse() {
    __shared__ float red[256];
    int row = blockIdx.x, tid = threadIdx.x;
    float2 p = (tid < NCH) ? g_part[(size_t)row * NCH + tid] : make_float2(-3.4e38f, 0.f);
    red[tid] = p.x; __syncthreads();
    for (int s = 128; s > 0; s >>= 1) {
        if (tid < s) red[tid] = fmaxf(red[tid], red[tid + s]);
        __syncthreads();
    }
    float gmax = red[0]; __syncthreads();
    red[tid] = p.y * exp2f((p.x - gmax) * L2E);
    __syncthreads();
    for (int s = 128; s > 0; s >>= 1) {
        if (tid < s) red[tid] += red[tid + s];
        __syncthreads();
    }
    if (tid == 0) g_lse[row] = gmax + LN2 * log2f(red[0]);
}

// ---------------- K6: exact fp32 gold logit per row ----------------
__global__ void k_gold(const float* __restrict__ hid, const float* __restrict__ W,
                       const float* __restrict__ fb, const float* __restrict__ bb) {
    __shared__ float red[256];
    int row = blockIdx.x, tid = threadIdx.x;
    int M = g_hdr[2], Nf = g_hdr[0];
    if (row >= M) return;
    int src = g_ctx[row], tok = g_tok[row];
    const float4* h4 = reinterpret_cast<const float4*>(
        hid + (size_t)src * 2 * DIMK + (row < Nf ? 0 : DIMK));
    const float4* w4 = reinterpret_cast<const float4*>(W + (size_t)tok * DIMK);
    float4 a = h4[tid], b = w4[tid];
    red[tid] = a.x * b.x + a.y * b.y + a.z * b.z + a.w * b.w;
    __syncthreads();
    for (int s = 128; s > 0; s >>= 1) {
        if (tid < s) red[tid] += red[tid + s];
        __syncthreads();
    }
    if (tid == 0) g_gold[row] = red[0] + (row < Nf ? fb[tok] : bb[tok]);
}

// ---------------- K7: final scalar ----------------
__global__ void k_final(float* __restrict__ out) {
    __shared__ float red[1024];
    int tid = threadIdx.x, M = g_hdr[2];
    float a = 0.f;
    for (int r = tid; r < M; r += 1024) a += g_lse[r] - g_gold[r];
    red[tid] = a; __syncthreads();
    for (int s = 512; s > 0; s >>= 1) {
        if (tid < s) red[tid] += red[tid + s];
        __syncthreads();
    }
    if (tid == 0) out[0] = red[0] / g_denom;
}

// ---------------- launch ----------------
extern "C" void kernel_launch(void* const* d_in, const int* in_sizes, int n_in,
                              void* d_out, int out_size) {
    const float* hid  = (const float*)d_in[0];
    const float* W    = (const float*)d_in[1];
    const float* fb   = (const float*)d_in[2];
    const float* bb   = (const float*)d_in[3];
    const int*   sent = (const int*)d_in[4];
    const int*   bs   = (const int*)d_in[5];
    int total = in_sizes[4];
    int T     = in_sizes[5];

    cudaFuncSetAttribute(k_gemm, cudaFuncAttributeMaxDynamicSharedMemorySize, GEMM_SMEM);

    k_build<<<1, 256>>>(bs, sent, T, total);
    k_gather<<<MP, 256>>>(hid);
    k_wconv<<<4096, 256>>>(W);
    k_gemm<<<dim3(NCH, MP / 128), 256, GEMM_SMEM>>>(fb, bb);
    k_lse<<<MP, 256>>>();
    k_gold<<<MP, 256>>>(hid, W, fb, bb);
    k_final<<<1, 1024>>>((float*)d_out);
}

// round 5
// speedup vs baseline: 1.0850x; 1.0081x over previous
#include <cuda_runtime.h>
#include <cuda_bf16.h>
#include <cstdint>

// ---------------- Problem constants (dataset-fixed) ----------------
#define DIMK   1024            // hidden dim per direction
#define VOCABN 32000           // vocab
#define MP     3712            // padded packed-row count, 29 tiles of 128
#define NCH    (VOCABN / 128)  // 250 vocab chunks of 128
#define KCH    (DIMK / 64)     // 16 K-chunks of 64 bf16
#define L2E    1.4426950408889634f
#define LN2    0.6931471805599453f

// ---------------- Scratch (static device globals; no allocs) ----------------
__device__ __nv_bfloat16 g_A[(size_t)MP * DIMK];        // gathered ctx rows, bf16
__device__ __nv_bfloat16 g_W[(size_t)VOCABN * DIMK];    // weight, bf16
__device__ float2        g_part[(size_t)MP * NCH];      // per (row, chunk): {max, sumexp}
__device__ float         g_lse[MP];
__device__ float         g_gold[MP];
__device__ int           g_ctx[MP];
__device__ int           g_tok[MP];
__device__ int           g_hdr[4];                      // Nf, Nb, M
__device__ float         g_denom;

// ---------------- PTX helpers (base ISA: cp.async / ldmatrix / mma.sync) ----
__device__ __forceinline__ uint32_t smem_u32(const void* p) {
    uint32_t a;
    asm("{ .reg .u64 t; cvta.to.shared.u64 t, %1; cvt.u32.u64 %0, t; }" : "=r"(a) : "l"(p));
    return a;
}
__device__ __forceinline__ void cp_async16(uint32_t saddr, const void* gaddr) {
    asm volatile("cp.async.cg.shared.global [%0], [%1], 16;" :: "r"(saddr), "l"(gaddr));
}
__device__ __forceinline__ void cp_commit() { asm volatile("cp.async.commit_group;" ::: "memory"); }
__device__ __forceinline__ void cp_wait1()  { asm volatile("cp.async.wait_group 1;" ::: "memory"); }

__device__ __forceinline__ void ldmatrix_x4(uint32_t& r0, uint32_t& r1, uint32_t& r2, uint32_t& r3,
                                            uint32_t addr) {
    asm volatile("ldmatrix.sync.aligned.m8n8.x4.shared.b16 {%0,%1,%2,%3}, [%4];"
                 : "=r"(r0), "=r"(r1), "=r"(r2), "=r"(r3) : "r"(addr));
}
__device__ __forceinline__ void mma16816(float* c,
                                         uint32_t a0, uint32_t a1, uint32_t a2, uint32_t a3,
                                         uint32_t b0, uint32_t b1) {
    asm volatile(
        "mma.sync.aligned.m16n8k16.row.col.f32.bf16.bf16.f32 "
        "{%0,%1,%2,%3}, {%4,%5,%6,%7}, {%8,%9}, {%0,%1,%2,%3};"
        : "+f"(c[0]), "+f"(c[1]), "+f"(c[2]), "+f"(c[3])
        : "r"(a0), "r"(a1), "r"(a2), "r"(a3), "r"(b0), "r"(b1));
}

// online-softmax pair combine
__device__ __forceinline__ void lse_combine(float& m, float& s, float m2, float s2) {
    float mx = fmaxf(m, m2);
    s = s * exp2f((m - mx) * L2E) + s2 * exp2f((m2 - mx) * L2E);
    m = mx;
}

// ---------------- K1: index build ----------------
__global__ void k_build(const int* __restrict__ bs, const int* __restrict__ sent, int T, int total) {
    __shared__ int off[257];
    int tid = threadIdx.x;
    if (tid == 0) {
        int acc = 0;
        for (int t = 0; t < T; ++t) { off[t] = acc; acc += bs[t]; }
        off[T] = acc;
    }
    __syncthreads();
    int rb = 0;
    for (int t = 1; t < T; ++t) {              // forward: h[t-1] predicts tok[t]
        int n = bs[t];
        for (int j = tid; j < n; j += blockDim.x) {
            g_ctx[rb + j] = off[t - 1] + j;
            g_tok[rb + j] = sent[off[t] + j];
        }
        rb += n;
    }
    int Nf = rb;
    for (int i = 1; i < T - 1; ++i) {          // backward: h[i+1] predicts tok[i]
        int n = bs[i + 1];
        for (int j = tid; j < n; j += blockDim.x) {
            g_ctx[rb + j] = off[i + 1] + j;
            g_tok[rb + j] = sent[off[i] + j];
        }
        rb += n;
    }
    int M = rb;
    for (int r = M + tid; r < MP; r += blockDim.x) { g_ctx[r] = 0; g_tok[r] = 0; }
    if (tid == 0) {
        g_hdr[0] = Nf; g_hdr[1] = M - Nf; g_hdr[2] = M;
        g_denom = (float)(2 * total - bs[0] - bs[T - 1]);
    }
}

// ---------------- K2: gather ctx rows -> bf16 A (zero pad rows) ----------------
__global__ void k_gather(const float* __restrict__ hid) {
    int row = blockIdx.x, tid = threadIdx.x;
    int M = g_hdr[2], Nf = g_hdr[0];
    uint2* dst = reinterpret_cast<uint2*>(&g_A[(size_t)row * DIMK]);
    if (row < M) {
        int src = g_ctx[row];
        const float4* p = reinterpret_cast<const float4*>(
            hid + (size_t)src * 2 * DIMK + (row < Nf ? 0 : DIMK));
        float4 v = p[tid];
        __nv_bfloat162 lo = __floats2bfloat162_rn(v.x, v.y);
        __nv_bfloat162 hi = __floats2bfloat162_rn(v.z, v.w);
        uint2 o;
        o.x = *reinterpret_cast<uint32_t*>(&lo);
        o.y = *reinterpret_cast<uint32_t*>(&hi);
        dst[tid] = o;
    } else {
        dst[tid] = make_uint2(0u, 0u);
    }
}

// ---------------- K3: weight fp32 -> bf16 ----------------
__global__ void k_wconv(const float* __restrict__ W) {
    const int n4 = VOCABN * DIMK / 4;
    for (int i = blockIdx.x * blockDim.x + threadIdx.x; i < n4; i += gridDim.x * blockDim.x) {
        float4 v = reinterpret_cast<const float4*>(W)[i];
        __nv_bfloat162 lo = __floats2bfloat162_rn(v.x, v.y);
        __nv_bfloat162 hi = __floats2bfloat162_rn(v.z, v.w);
        uint2 o;
        o.x = *reinterpret_cast<uint32_t*>(&lo);
        o.y = *reinterpret_cast<uint32_t*>(&hi);
        reinterpret_cast<uint2*>(g_W)[i] = o;
    }
}

// ---------------- K4: mma.sync GEMM + fused online max/sumexp epilogue ----------------
// grid = (NCH, MP/128), 256 threads (8 warps as 4(M) x 2(N)).
// CTA tile 128(M) x 128(N) x 64(K); warp tile 32(M) x 64(N).
// 3-stage cp.async pipeline, ONE __syncthreads per K-chunk.
#define GEMM_SMEM 102400
__global__ __launch_bounds__(256, 2)
void k_gemm(const float* __restrict__ fbias, const float* __restrict__ bbias) {
    extern __shared__ char dynsmem[];
    uint32_t raw = smem_u32(dynsmem);
    uint32_t pad = (1024u - (raw & 1023u)) & 1023u;
    uint32_t sb  = raw + pad;
    char* base   = dynsmem + pad;

    const uint32_t sA[3] = { sb,          sb + 16384, sb + 32768 };
    const uint32_t sB[3] = { sb + 49152,  sb + 65536, sb + 81920 };
    float*  biasF = reinterpret_cast<float*>(base + 98304);          // 128 f
    float*  biasB = biasF + 128;                                     // 128 f
    float2* scr   = reinterpret_cast<float2*>(base + 99328);         // [128][2]

    int tid  = threadIdx.x;
    int warp = tid >> 5;
    int lane = tid & 31;
    int wm   = warp >> 1;        // 0..3  (M strip of 32)
    int wn   = warp & 1;         // 0..1  (N strip of 64)
    int nb = blockIdx.x, mb = blockIdx.y;
    int n0 = nb * 128, m0 = mb * 128;

    if (tid < 128) biasF[tid] = fbias[n0 + tid];
    else           biasB[tid - 128] = bbias[n0 + tid - 128];

    const __nv_bfloat16* Ag = g_A + (size_t)m0 * DIMK;
    const __nv_bfloat16* Bg = g_W + (size_t)n0 * DIMK;

    // tile loader: 128 rows x 64 bf16 (128B/row), SW128-style swizzle, 16B cp.async
    auto load_tile = [&](uint32_t sdst, const __nv_bfloat16* src, int k0) {
        #pragma unroll
        for (int i = 0; i < 4; ++i) {
            int idx = tid + i * 256;
            int r = idx >> 3, c = idx & 7;
            uint32_t off = (uint32_t)(r * 128 + c * 16);
            uint32_t sw  = off ^ ((off >> 3) & 0x70u);
            cp_async16(sdst + sw, src + (size_t)r * DIMK + k0 + c * 8);
        }
    };

    // prologue: stages 0,1 in flight (group g <-> K-chunk g)
    load_tile(sA[0], Ag, 0);  load_tile(sB[0], Bg, 0);  cp_commit();
    load_tile(sA[1], Ag, 64); load_tile(sB[1], Bg, 64); cp_commit();

    float c[2][8][4];
    #pragma unroll
    for (int mi = 0; mi < 2; ++mi)
        #pragma unroll
        for (int nj = 0; nj < 8; ++nj)
            #pragma unroll
            for (int q = 0; q < 4; ++q) c[mi][nj][q] = 0.f;

    // fragment row/col components (constant across chunks)
    const uint32_t a_row = (uint32_t)(wm * 32 + (lane & 15));        // + mi*16
    const uint32_t a_kb  = (uint32_t)((lane >> 4) << 4);             // 0 or 16 bytes
    const uint32_t b_row = (uint32_t)(wn * 64 + (lane & 7) + ((lane >> 4) << 3)); // + nj2*16
    const uint32_t b_kb  = (uint32_t)(((lane >> 3) & 1) << 4);       // 0 or 16 bytes

    int stage = 0;
    for (int kc = 0; kc < KCH; ++kc) {
        // stage kc resident once <=1 group pending (groups 0..kc complete)
        cp_wait1();
        __syncthreads();   // also: everyone done reading stage (kc-1) -> safe to refill

        // issue next load FIRST so LSU overlaps the MMA block below
        int kn = kc + 2;
        int nstage = stage + 2; if (nstage >= 3) nstage -= 3;
        if (kn < KCH) { load_tile(sA[nstage], Ag, kn * 64); load_tile(sB[nstage], Bg, kn * 64); }
        cp_commit();       // uniform group accounting (empty groups ok)

        uint32_t abase = sA[stage], bbase = sB[stage];
        #pragma unroll
        for (int s = 0; s < 4; ++s) {
            uint32_t a[2][4];
            #pragma unroll
            for (int mi = 0; mi < 2; ++mi) {
                uint32_t off = (a_row + mi * 16) * 128u + (uint32_t)(s * 32) + a_kb;
                off ^= (off >> 3) & 0x70u;
                ldmatrix_x4(a[mi][0], a[mi][1], a[mi][2], a[mi][3], abase + off);
            }
            #pragma unroll
            for (int nj2 = 0; nj2 < 4; ++nj2) {
                uint32_t b0, b1, b2, b3;
                uint32_t off = (b_row + nj2 * 16) * 128u + (uint32_t)(s * 32) + b_kb;
                off ^= (off >> 3) & 0x70u;
                ldmatrix_x4(b0, b1, b2, b3, bbase + off);
                #pragma unroll
                for (int mi = 0; mi < 2; ++mi) {
                    mma16816(c[mi][2 * nj2],     a[mi][0], a[mi][1], a[mi][2], a[mi][3], b0, b1);
                    mma16816(c[mi][2 * nj2 + 1], a[mi][0], a[mi][1], a[mi][2], a[mi][3], b2, b3);
                }
            }
        }
        ++stage; if (stage == 3) stage = 0;
    }

    // ----- epilogue: per-row online max/sumexp over this warp's 64 cols -----
    int Nf = g_hdr[0];
    int cb = wn * 64 + (lane & 3) * 2;      // local col of c[.][nj][0]
    float mv[2][2], sv[2][2];
    const float* bp[2][2];
    int lrow[2][2];
    #pragma unroll
    for (int mi = 0; mi < 2; ++mi)
        #pragma unroll
        for (int h = 0; h < 2; ++h) {
            lrow[mi][h] = wm * 32 + mi * 16 + h * 8 + (lane >> 2);
            bp[mi][h]   = (m0 + lrow[mi][h] < Nf) ? biasF : biasB;
            mv[mi][h]   = -3.4e38f;
            sv[mi][h]   = 0.f;
        }
    #pragma unroll
    for (int nj = 0; nj < 8; ++nj) {
        int col = cb + nj * 8;
        #pragma unroll
        for (int mi = 0; mi < 2; ++mi) {
            float v0 = c[mi][nj][0] + bp[mi][0][col];
            float v1 = c[mi][nj][1] + bp[mi][0][col + 1];
            float mx = fmaxf(v0, v1);
            if (mx > mv[mi][0]) { sv[mi][0] *= exp2f((mv[mi][0] - mx) * L2E); mv[mi][0] = mx; }
            sv[mi][0] += exp2f((v0 - mv[mi][0]) * L2E) + exp2f((v1 - mv[mi][0]) * L2E);

            float w0 = c[mi][nj][2] + bp[mi][1][col];
            float w1 = c[mi][nj][3] + bp[mi][1][col + 1];
            mx = fmaxf(w0, w1);
            if (mx > mv[mi][1]) { sv[mi][1] *= exp2f((mv[mi][1] - mx) * L2E); mv[mi][1] = mx; }
            sv[mi][1] += exp2f((w0 - mv[mi][1]) * L2E) + exp2f((w1 - mv[mi][1]) * L2E);
        }
    }
    // quad reduce (lanes differing in bits 0,1 share each row)
    #pragma unroll
    for (int mi = 0; mi < 2; ++mi)
        #pragma unroll
        for (int h = 0; h < 2; ++h)
            #pragma unroll
            for (int d = 1; d <= 2; d <<= 1) {
                float m2 = __shfl_xor_sync(0xffffffffu, mv[mi][h], d);
                float s2 = __shfl_xor_sync(0xffffffffu, sv[mi][h], d);
                lse_combine(mv[mi][h], sv[mi][h], m2, s2);
            }
    if ((lane & 3) == 0) {
        #pragma unroll
        for (int mi = 0; mi < 2; ++mi)
            #pragma unroll
            for (int h = 0; h < 2; ++h)
                scr[lrow[mi][h] * 2 + wn] = make_float2(mv[mi][h], sv[mi][h]);
    }
    __syncthreads();
    if (tid < 128) {
        float2 p0 = scr[tid * 2 + 0], p1 = scr[tid * 2 + 1];
        lse_combine(p0.x, p0.y, p1.x, p1.y);
        g_part[(size_t)(m0 + tid) * NCH + nb] = p0;
    }
}

// ---------------- K5: per-row lse reduce over 250 partials ----------------
__global__ void k_lse() {
    __shared__ float red[256];
    int row = blockIdx.x, tid = threadIdx.x;
    float2 p = (tid < NCH) ? g_part[(size_t)row * NCH + tid] : make_float2(-3.4e38f, 0.f);
    red[tid] = p.x; __syncthreads();
    for (int s = 128; s > 0; s >>= 1) {
        if (tid < s) red[tid] = fmaxf(red[tid], red[tid + s]);
        __syncthreads();
    }
    float gmax = red[0]; __syncthreads();
    red[tid] = p.y * exp2f((p.x - gmax) * L2E);
    __syncthreads();
    for (int s = 128; s > 0; s >>= 1) {
        if (tid < s) red[tid] += red[tid + s];
        __syncthreads();
    }
    if (tid == 0) g_lse[row] = gmax + LN2 * log2f(red[0]);
}

// ---------------- K6: exact fp32 gold logit per row ----------------
__global__ void k_gold(const float* __restrict__ hid, const float* __restrict__ W,
                       const float* __restrict__ fb, const float* __restrict__ bb) {
    __shared__ float red[256];
    int row = blockIdx.x, tid = threadIdx.x;
    int M = g_hdr[2], Nf = g_hdr[0];
    if (row >= M) return;
    int src = g_ctx[row], tok = g_tok[row];
    const float4* h4 = reinterpret_cast<const float4*>(
        hid + (size_t)src * 2 * DIMK + (row < Nf ? 0 : DIMK));
    const float4* w4 = reinterpret_cast<const float4*>(W + (size_t)tok * DIMK);
    float4 a = h4[tid], b = w4[tid];
    red[tid] = a.x * b.x + a.y * b.y + a.z * b.z + a.w * b.w;
    __syncthreads();
    for (int s = 128; s > 0; s >>= 1) {
        if (tid < s) red[tid] += red[tid + s];
        __syncthreads();
    }
    if (tid == 0) g_gold[row] = red[0] + (row < Nf ? fb[tok] : bb[tok]);
}

// ---------------- K7: final scalar ----------------
__global__ void k_final(float* __restrict__ out) {
    __shared__ float red[1024];
    int tid = threadIdx.x, M = g_hdr[2];
    float a = 0.f;
    for (int r = tid; r < M; r += 1024) a += g_lse[r] - g_gold[r];
    red[tid] = a; __syncthreads();
    for (int s = 512; s > 0; s >>= 1) {
        if (tid < s) red[tid] += red[tid + s];
        __syncthreads();
    }
    if (tid == 0) out[0] = red[0] / g_denom;
}

// ---------------- launch ----------------
extern "C" void kernel_launch(void* const* d_in, const int* in_sizes, int n_in,
                              void* d_out, int out_size) {
    const float* hid  = (const float*)d_in[0];
    const float* W    = (const float*)d_in[1];
    const float* fb   = (const float*)d_in[2];
    const float* bb   = (const float*)d_in[3];
    const int*   sent = (const int*)d_in[4];
    const int*   bs   = (const int*)d_in[5];
    int total = in_sizes[4];
    int T     = in_sizes[5];

    cudaFuncSetAttribute(k_gemm, cudaFuncAttributeMaxDynamicSharedMemorySize, GEMM_SMEM);

    k_build<<<1, 256>>>(bs, sent, T, total);
    k_gather<<<MP, 256>>>(hid);
    k_wconv<<<4096, 256>>>(W);
    k_gemm<<<dim3(NCH, MP / 128), 256, GEMM_SMEM>>>(fb, bb);
    k_lse<<<MP, 256>>>();
    k_gold<<<MP, 256>>>(hid, W, fb, bb);
    k_final<<<1, 1024>>>((float*)d_out);
}

// round 6
// speedup vs baseline: 1.1114x; 1.0244x over previous
#include <cuda_runtime.h>
#include <cuda_bf16.h>
#include <cstdint>

// ---------------- Problem constants (dataset-fixed) ----------------
#define DIMK   1024            // hidden dim per direction
#define VOCABN 32000           // vocab
#define MP     3712            // padded packed-row count, 29 tiles of 128
#define NCH    (VOCABN / 128)  // 250 vocab chunks of 128
#define KCH    (DIMK / 64)     // 16 K-chunks of 64 bf16
#define L2E    1.4426950408889634f
#define LN2    0.6931471805599453f

// ---------------- Scratch (static device globals; no allocs) ----------------
__device__ __nv_bfloat16 g_A[(size_t)MP * DIMK];        // gathered ctx rows, bf16
__device__ __nv_bfloat16 g_W[(size_t)VOCABN * DIMK];    // weight, bf16
__device__ float2        g_part[(size_t)MP * NCH];      // per (row, chunk): {max, sumexp}
__device__ float         g_lse[MP];
__device__ float         g_gold[MP];
__device__ int           g_ctx[MP];
__device__ int           g_tok[MP];
__device__ int           g_hdr[4];                      // Nf, Nb, M
__device__ float         g_denom;

// ---------------- PTX helpers (base ISA: cp.async / ldmatrix / mma.sync) ----
__device__ __forceinline__ uint32_t smem_u32(const void* p) {
    uint32_t a;
    asm("{ .reg .u64 t; cvta.to.shared.u64 t, %1; cvt.u32.u64 %0, t; }" : "=r"(a) : "l"(p));
    return a;
}
__device__ __forceinline__ void cp_async16(uint32_t saddr, const void* gaddr) {
    asm volatile("cp.async.cg.shared.global [%0], [%1], 16;" :: "r"(saddr), "l"(gaddr));
}
__device__ __forceinline__ void cp_commit() { asm volatile("cp.async.commit_group;" ::: "memory"); }
__device__ __forceinline__ void cp_wait1()  { asm volatile("cp.async.wait_group 1;" ::: "memory"); }

__device__ __forceinline__ void ldmatrix_x4(uint32_t& r0, uint32_t& r1, uint32_t& r2, uint32_t& r3,
                                            uint32_t addr) {
    asm volatile("ldmatrix.sync.aligned.m8n8.x4.shared.b16 {%0,%1,%2,%3}, [%4];"
                 : "=r"(r0), "=r"(r1), "=r"(r2), "=r"(r3) : "r"(addr));
}
__device__ __forceinline__ void mma16816(float* c,
                                         uint32_t a0, uint32_t a1, uint32_t a2, uint32_t a3,
                                         uint32_t b0, uint32_t b1) {
    asm volatile(
        "mma.sync.aligned.m16n8k16.row.col.f32.bf16.bf16.f32 "
        "{%0,%1,%2,%3}, {%4,%5,%6,%7}, {%8,%9}, {%0,%1,%2,%3};"
        : "+f"(c[0]), "+f"(c[1]), "+f"(c[2]), "+f"(c[3])
        : "r"(a0), "r"(a1), "r"(a2), "r"(a3), "r"(b0), "r"(b1));
}

// online-softmax pair combine
__device__ __forceinline__ void lse_combine(float& m, float& s, float m2, float s2) {
    float mx = fmaxf(m, m2);
    s = s * exp2f((m - mx) * L2E) + s2 * exp2f((m2 - mx) * L2E);
    m = mx;
}

// ---------------- K1: index build ----------------
__global__ void k_build(const int* __restrict__ bs, const int* __restrict__ sent, int T, int total) {
    __shared__ int off[257];
    int tid = threadIdx.x;
    if (tid == 0) {
        int acc = 0;
        for (int t = 0; t < T; ++t) { off[t] = acc; acc += bs[t]; }
        off[T] = acc;
    }
    __syncthreads();
    int rb = 0;
    for (int t = 1; t < T; ++t) {              // forward: h[t-1] predicts tok[t]
        int n = bs[t];
        for (int j = tid; j < n; j += blockDim.x) {
            g_ctx[rb + j] = off[t - 1] + j;
            g_tok[rb + j] = sent[off[t] + j];
        }
        rb += n;
    }
    int Nf = rb;
    for (int i = 1; i < T - 1; ++i) {          // backward: h[i+1] predicts tok[i]
        int n = bs[i + 1];
        for (int j = tid; j < n; j += blockDim.x) {
            g_ctx[rb + j] = off[i + 1] + j;
            g_tok[rb + j] = sent[off[i] + j];
        }
        rb += n;
    }
    int M = rb;
    for (int r = M + tid; r < MP; r += blockDim.x) { g_ctx[r] = 0; g_tok[r] = 0; }
    if (tid == 0) {
        g_hdr[0] = Nf; g_hdr[1] = M - Nf; g_hdr[2] = M;
        g_denom = (float)(2 * total - bs[0] - bs[T - 1]);
    }
}

// ---------------- K2: gather ctx rows -> bf16 A (zero pad rows) ----------------
__global__ void k_gather(const float* __restrict__ hid) {
    int row = blockIdx.x, tid = threadIdx.x;
    int M = g_hdr[2], Nf = g_hdr[0];
    uint2* dst = reinterpret_cast<uint2*>(&g_A[(size_t)row * DIMK]);
    if (row < M) {
        int src = g_ctx[row];
        const float4* p = reinterpret_cast<const float4*>(
            hid + (size_t)src * 2 * DIMK + (row < Nf ? 0 : DIMK));
        float4 v = p[tid];
        __nv_bfloat162 lo = __floats2bfloat162_rn(v.x, v.y);
        __nv_bfloat162 hi = __floats2bfloat162_rn(v.z, v.w);
        uint2 o;
        o.x = *reinterpret_cast<uint32_t*>(&lo);
        o.y = *reinterpret_cast<uint32_t*>(&hi);
        dst[tid] = o;
    } else {
        dst[tid] = make_uint2(0u, 0u);
    }
}

// ---------------- K3: weight fp32 -> bf16 ----------------
__global__ void k_wconv(const float* __restrict__ W) {
    const int n4 = VOCABN * DIMK / 4;
    for (int i = blockIdx.x * blockDim.x + threadIdx.x; i < n4; i += gridDim.x * blockDim.x) {
        float4 v = reinterpret_cast<const float4*>(W)[i];
        __nv_bfloat162 lo = __floats2bfloat162_rn(v.x, v.y);
        __nv_bfloat162 hi = __floats2bfloat162_rn(v.z, v.w);
        uint2 o;
        o.x = *reinterpret_cast<uint32_t*>(&lo);
        o.y = *reinterpret_cast<uint32_t*>(&hi);
        reinterpret_cast<uint2*>(g_W)[i] = o;
    }
}

// ---------------- K4: mma.sync GEMM + fused softmax-partial epilogue ----------------
// grid = (NCH, MP/128), 256 threads (8 warps as 4(M) x 2(N)).
// CTA tile 128(M) x 128(N) x 64(K); warp tile 32(M) x 64(N).
// 3-stage cp.async pipeline, ONE __syncthreads per K-chunk.
// Fragments double-buffered at s-granularity; swizzle hoisted out of inner loop.
#define GEMM_SMEM 102400
__global__ __launch_bounds__(256, 2)
void k_gemm(const float* __restrict__ fbias, const float* __restrict__ bbias) {
    extern __shared__ char dynsmem[];
    uint32_t raw = smem_u32(dynsmem);
    uint32_t pad = (1024u - (raw & 1023u)) & 1023u;
    uint32_t sb  = raw + pad;
    char* base   = dynsmem + pad;

    const uint32_t sA[3] = { sb,          sb + 16384, sb + 32768 };
    const uint32_t sB[3] = { sb + 49152,  sb + 65536, sb + 81920 };
    float*  biasF = reinterpret_cast<float*>(base + 98304);          // 128 f
    float*  biasB = biasF + 128;                                     // 128 f
    float2* scr   = reinterpret_cast<float2*>(base + 99328);         // [128][2]

    int tid  = threadIdx.x;
    int warp = tid >> 5;
    int lane = tid & 31;
    int wm   = warp >> 1;        // 0..3  (M strip of 32)
    int wn   = warp & 1;         // 0..1  (N strip of 64)
    int nb = blockIdx.x, mb = blockIdx.y;
    int n0 = nb * 128, m0 = mb * 128;

    if (tid < 128) biasF[tid] = fbias[n0 + tid];
    else           biasB[tid - 128] = bbias[n0 + tid - 128];

    const __nv_bfloat16* Ag = g_A + (size_t)m0 * DIMK;
    const __nv_bfloat16* Bg = g_W + (size_t)n0 * DIMK;

    // tile loader: 128 rows x 64 bf16 (128B/row), SW128-style swizzle, 16B cp.async
    auto load_tile = [&](uint32_t sdst, const __nv_bfloat16* src, int k0) {
        #pragma unroll
        for (int i = 0; i < 4; ++i) {
            int idx = tid + i * 256;
            int r = idx >> 3, c = idx & 7;
            uint32_t off = (uint32_t)(r * 128 + c * 16);
            uint32_t sw  = off ^ ((off >> 3) & 0x70u);
            cp_async16(sdst + sw, src + (size_t)r * DIMK + k0 + c * 8);
        }
    };

    // prologue: stages 0,1 in flight (group g <-> K-chunk g)
    load_tile(sA[0], Ag, 0);  load_tile(sB[0], Bg, 0);  cp_commit();
    load_tile(sA[1], Ag, 64); load_tile(sB[1], Bg, 64); cp_commit();

    float c[2][8][4];
    #pragma unroll
    for (int mi = 0; mi < 2; ++mi)
        #pragma unroll
        for (int nj = 0; nj < 8; ++nj)
            #pragma unroll
            for (int q = 0; q < 4; ++q) c[mi][nj][q] = 0.f;

    // fragment geometry (constant across chunks)
    const uint32_t a_row = (uint32_t)(wm * 32 + (lane & 15));        // + mi*16
    const uint32_t a_kb  = (uint32_t)((lane >> 4) << 4);             // 0 or 16 bytes
    const uint32_t b_row = (uint32_t)(wn * 64 + (lane & 7) + ((lane >> 4) << 3)); // + nj2*16
    const uint32_t b_kb  = (uint32_t)(((lane >> 3) & 1) << 4);       // 0 or 16 bytes
    // swizzle hoist: for 128B rows, XOR mask = (row & 7) << 4 (depends only on row)
    const uint32_t km_a  = a_kb ^ ((a_row & 7u) << 4);
    const uint32_t km_b  = b_kb ^ ((b_row & 7u) << 4);
    const uint32_t a_ro[2] = { a_row * 128u, (a_row + 16u) * 128u };
    const uint32_t b_ro[4] = { b_row * 128u, (b_row + 16u) * 128u,
                               (b_row + 32u) * 128u, (b_row + 48u) * 128u };

    int stage = 0;
    for (int kc = 0; kc < KCH; ++kc) {
        cp_wait1();        // stage kc resident
        __syncthreads();   // stage (kc-1) fully consumed -> refillable

        // issue next global load FIRST so LSU overlaps the MMA block below
        int kn = kc + 2;
        int nstage = stage + 2; if (nstage >= 3) nstage -= 3;
        if (kn < KCH) { load_tile(sA[nstage], Ag, kn * 64); load_tile(sB[nstage], Bg, kn * 64); }
        cp_commit();       // uniform group accounting (empty groups ok)

        const uint32_t aAd0 = sA[stage] + a_ro[0], aAd1 = sA[stage] + a_ro[1];
        const uint32_t bAd0 = sB[stage] + b_ro[0], bAd1 = sB[stage] + b_ro[1];
        const uint32_t bAd2 = sB[stage] + b_ro[2], bAd3 = sB[stage] + b_ro[3];

        uint32_t af[2][2][4];   // [buf][mi][reg]
        uint32_t bf[2][4][4];   // [buf][nj2][reg]

        // load s=0 fragments into buf 0
        {
            uint32_t ta = 0u ^ km_a, tb = 0u ^ km_b;
            ldmatrix_x4(af[0][0][0], af[0][0][1], af[0][0][2], af[0][0][3], aAd0 + ta);
            ldmatrix_x4(af[0][1][0], af[0][1][1], af[0][1][2], af[0][1][3], aAd1 + ta);
            ldmatrix_x4(bf[0][0][0], bf[0][0][1], bf[0][0][2], bf[0][0][3], bAd0 + tb);
            ldmatrix_x4(bf[0][1][0], bf[0][1][1], bf[0][1][2], bf[0][1][3], bAd1 + tb);
            ldmatrix_x4(bf[0][2][0], bf[0][2][1], bf[0][2][2], bf[0][2][3], bAd2 + tb);
            ldmatrix_x4(bf[0][3][0], bf[0][3][1], bf[0][3][2], bf[0][3][3], bAd3 + tb);
        }
        #pragma unroll
        for (int s = 0; s < 4; ++s) {
            int cur = s & 1, nxt = cur ^ 1;
            if (s < 3) {   // prefetch fragments for s+1 while MMAs below run
                uint32_t ta = ((uint32_t)(s + 1) * 32u) ^ km_a;
                uint32_t tb = ((uint32_t)(s + 1) * 32u) ^ km_b;
                ldmatrix_x4(af[nxt][0][0], af[nxt][0][1], af[nxt][0][2], af[nxt][0][3], aAd0 + ta);
                ldmatrix_x4(af[nxt][1][0], af[nxt][1][1], af[nxt][1][2], af[nxt][1][3], aAd1 + ta);
                ldmatrix_x4(bf[nxt][0][0], bf[nxt][0][1], bf[nxt][0][2], bf[nxt][0][3], bAd0 + tb);
                ldmatrix_x4(bf[nxt][1][0], bf[nxt][1][1], bf[nxt][1][2], bf[nxt][1][3], bAd1 + tb);
                ldmatrix_x4(bf[nxt][2][0], bf[nxt][2][1], bf[nxt][2][2], bf[nxt][2][3], bAd2 + tb);
                ldmatrix_x4(bf[nxt][3][0], bf[nxt][3][1], bf[nxt][3][2], bf[nxt][3][3], bAd3 + tb);
            }
            #pragma unroll
            for (int nj2 = 0; nj2 < 4; ++nj2) {
                #pragma unroll
                for (int mi = 0; mi < 2; ++mi) {
                    mma16816(c[mi][2 * nj2],
                             af[cur][mi][0], af[cur][mi][1], af[cur][mi][2], af[cur][mi][3],
                             bf[cur][nj2][0], bf[cur][nj2][1]);
                    mma16816(c[mi][2 * nj2 + 1],
                             af[cur][mi][0], af[cur][mi][1], af[cur][mi][2], af[cur][mi][3],
                             bf[cur][nj2][2], bf[cur][nj2][3]);
                }
            }
        }
        ++stage; if (stage == 3) stage = 0;
    }

    // ----- epilogue: branch-free two-pass per-row max / exp-sum over 64 cols -----
    int Nf = g_hdr[0];
    int cb = wn * 64 + (lane & 3) * 2;      // local col of c[.][nj][0]
    const float* bp[2][2];
    int lrow[2][2];
    float mx[2][2], sm[2][2];
    #pragma unroll
    for (int mi = 0; mi < 2; ++mi)
        #pragma unroll
        for (int h = 0; h < 2; ++h) {
            lrow[mi][h] = wm * 32 + mi * 16 + h * 8 + (lane >> 2);
            bp[mi][h]   = (m0 + lrow[mi][h] < Nf) ? biasF : biasB;
            mx[mi][h]   = -3.4e38f;
            sm[mi][h]   = 0.f;
        }
    // pass 1: add bias in place, track per-lane max
    #pragma unroll
    for (int nj = 0; nj < 8; ++nj) {
        int col = cb + nj * 8;
        #pragma unroll
        for (int mi = 0; mi < 2; ++mi) {
            c[mi][nj][0] += bp[mi][0][col];
            c[mi][nj][1] += bp[mi][0][col + 1];
            c[mi][nj][2] += bp[mi][1][col];
            c[mi][nj][3] += bp[mi][1][col + 1];
            mx[mi][0] = fmaxf(mx[mi][0], fmaxf(c[mi][nj][0], c[mi][nj][1]));
            mx[mi][1] = fmaxf(mx[mi][1], fmaxf(c[mi][nj][2], c[mi][nj][3]));
        }
    }
    // quad max (lanes differing in bits 0,1 share each row)
    #pragma unroll
    for (int mi = 0; mi < 2; ++mi)
        #pragma unroll
        for (int h = 0; h < 2; ++h) {
            mx[mi][h] = fmaxf(mx[mi][h], __shfl_xor_sync(0xffffffffu, mx[mi][h], 1));
            mx[mi][h] = fmaxf(mx[mi][h], __shfl_xor_sync(0xffffffffu, mx[mi][h], 2));
        }
    // pass 2: exp-sum with shared row max
    #pragma unroll
    for (int nj = 0; nj < 8; ++nj) {
        #pragma unroll
        for (int mi = 0; mi < 2; ++mi) {
            sm[mi][0] += exp2f((c[mi][nj][0] - mx[mi][0]) * L2E)
                       + exp2f((c[mi][nj][1] - mx[mi][0]) * L2E);
            sm[mi][1] += exp2f((c[mi][nj][2] - mx[mi][1]) * L2E)
                       + exp2f((c[mi][nj][3] - mx[mi][1]) * L2E);
        }
    }
    #pragma unroll
    for (int mi = 0; mi < 2; ++mi)
        #pragma unroll
        for (int h = 0; h < 2; ++h) {
            sm[mi][h] += __shfl_xor_sync(0xffffffffu, sm[mi][h], 1);
            sm[mi][h] += __shfl_xor_sync(0xffffffffu, sm[mi][h], 2);
        }
    if ((lane & 3) == 0) {
        #pragma unroll
        for (int mi = 0; mi < 2; ++mi)
            #pragma unroll
            for (int h = 0; h < 2; ++h)
                scr[lrow[mi][h] * 2 + wn] = make_float2(mx[mi][h], sm[mi][h]);
    }
    __syncthreads();
    if (tid < 128) {
        float2 p0 = scr[tid * 2 + 0], p1 = scr[tid * 2 + 1];
        lse_combine(p0.x, p0.y, p1.x, p1.y);
        g_part[(size_t)(m0 + tid) * NCH + nb] = p0;
    }
}

// ---------------- K5: per-row lse reduce over 250 partials ----------------
__global__ void k_lse() {
    __shared__ float red[256];
    int row = blockIdx.x, tid = threadIdx.x;
    float2 p = (tid < NCH) ? g_part[(size_t)row * NCH + tid] : make_float2(-3.4e38f, 0.f);
    red[tid] = p.x; __syncthreads();
    for (int s = 128; s > 0; s >>= 1) {
        if (tid < s) red[tid] = fmaxf(red[tid], red[tid + s]);
        __syncthreads();
    }
    float gmax = red[0]; __syncthreads();
    red[tid] = p.y * exp2f((p.x - gmax) * L2E);
    __syncthreads();
    for (int s = 128; s > 0; s >>= 1) {
        if (tid < s) red[tid] += red[tid + s];
        __syncthreads();
    }
    if (tid == 0) g_lse[row] = gmax + LN2 * log2f(red[0]);
}

// ---------------- K6: exact fp32 gold logit per row ----------------
__global__ void k_gold(const float* __restrict__ hid, const float* __restrict__ W,
                       const float* __restrict__ fb, const float* __restrict__ bb) {
    __shared__ float red[256];
    int row = blockIdx.x, tid = threadIdx.x;
    int M = g_hdr[2], Nf = g_hdr[0];
    if (row >= M) return;
    int src = g_ctx[row], tok = g_tok[row];
    const float4* h4 = reinterpret_cast<const float4*>(
        hid + (size_t)src * 2 * DIMK + (row < Nf ? 0 : DIMK));
    const float4* w4 = reinterpret_cast<const float4*>(W + (size_t)tok * DIMK);
    float4 a = h4[tid], b = w4[tid];
    red[tid] = a.x * b.x + a.y * b.y + a.z * b.z + a.w * b.w;
    __syncthreads();
    for (int s = 128; s > 0; s >>= 1) {
        if (tid < s) red[tid] += red[tid + s];
        __syncthreads();
    }
    if (tid == 0) g_gold[row] = red[0] + (row < Nf ? fb[tok] : bb[tok]);
}

// ---------------- K7: final scalar ----------------
__global__ void k_final(float* __restrict__ out) {
    __shared__ float red[1024];
    int tid = threadIdx.x, M = g_hdr[2];
    float a = 0.f;
    for (int r = tid; r < M; r += 1024) a += g_lse[r] - g_gold[r];
    red[tid] = a; __syncthreads();
    for (int s = 512; s > 0; s >>= 1) {
        if (tid < s) red[tid] += red[tid + s];
        __syncthreads();
    }
    if (tid == 0) out[0] = red[0] / g_denom;
}

// ---------------- launch ----------------
extern "C" void kernel_launch(void* const* d_in, const int* in_sizes, int n_in,
                              void* d_out, int out_size) {
    const float* hid  = (const float*)d_in[0];
    const float* W    = (const float*)d_in[1];
    const float* fb   = (const float*)d_in[2];
    const float* bb   = (const float*)d_in[3];
    const int*   sent = (const int*)d_in[4];
    const int*   bs   = (const int*)d_in[5];
    int total = in_sizes[4];
    int T     = in_sizes[5];

    cudaFuncSetAttribute(k_gemm, cudaFuncAttributeMaxDynamicSharedMemorySize, GEMM_SMEM);

    k_build<<<1, 256>>>(bs, sent, T, total);
    k_gather<<<MP, 256>>>(hid);
    k_wconv<<<4096, 256>>>(W);
    k_gemm<<<dim3(NCH, MP / 128), 256, GEMM_SMEM>>>(fb, bb);
    k_lse<<<MP, 256>>>();
    k_gold<<<MP, 256>>>(hid, W, fb, bb);
    k_final<<<1, 1024>>>((float*)d_out);
}

// round 7
// speedup vs baseline: 1.3115x; 1.1800x over previous
#include <cuda_runtime.h>
#include <cuda_bf16.h>
#include <cstdint>

// ---------------- Problem constants (dataset-fixed) ----------------
#define DIMK   1024            // hidden dim per direction
#define VOCABN 32000           // vocab
#define MP     3712            // padded packed-row count, 29 tiles of 128
#define NCH    (VOCABN / 128)  // 250 vocab chunks of 128
#define KCH    (DIMK / 64)     // 16 K-chunks of 64 bf16
#define L2E    1.4426950408889634f
#define LN2    0.6931471805599453f

// ---------------- Scratch (static device globals; no allocs) ----------------
__device__ __nv_bfloat16 g_A[(size_t)MP * DIMK];        // gathered ctx rows, bf16
__device__ __nv_bfloat16 g_W[(size_t)VOCABN * DIMK];    // weight, bf16
__device__ float2        g_part[(size_t)MP * NCH];      // per (row, chunk): {max, sumexp}
__device__ float         g_lse[MP];
__device__ float         g_gold[MP];
__device__ int           g_ctx[MP];
__device__ int           g_tok[MP];
__device__ int           g_hdr[4];                      // Nf, Nb, M
__device__ float         g_denom;

// ---------------- PTX helpers (base ISA: cp.async / ldmatrix / mma.sync) ----
__device__ __forceinline__ uint32_t smem_u32(const void* p) {
    uint32_t a;
    asm("{ .reg .u64 t; cvta.to.shared.u64 t, %1; cvt.u32.u64 %0, t; }" : "=r"(a) : "l"(p));
    return a;
}
__device__ __forceinline__ void cp_async16(uint32_t saddr, const void* gaddr) {
    asm volatile("cp.async.cg.shared.global [%0], [%1], 16;" :: "r"(saddr), "l"(gaddr));
}
__device__ __forceinline__ void cp_commit() { asm volatile("cp.async.commit_group;" ::: "memory"); }
__device__ __forceinline__ void cp_wait1()  { asm volatile("cp.async.wait_group 1;" ::: "memory"); }

__device__ __forceinline__ void ldmatrix_x4(uint32_t& r0, uint32_t& r1, uint32_t& r2, uint32_t& r3,
                                            uint32_t addr) {
    asm volatile("ldmatrix.sync.aligned.m8n8.x4.shared.b16 {%0,%1,%2,%3}, [%4];"
                 : "=r"(r0), "=r"(r1), "=r"(r2), "=r"(r3) : "r"(addr));
}
__device__ __forceinline__ void mma16816(float* c,
                                         uint32_t a0, uint32_t a1, uint32_t a2, uint32_t a3,
                                         uint32_t b0, uint32_t b1) {
    asm volatile(
        "mma.sync.aligned.m16n8k16.row.col.f32.bf16.bf16.f32 "
        "{%0,%1,%2,%3}, {%4,%5,%6,%7}, {%8,%9}, {%0,%1,%2,%3};"
        : "+f"(c[0]), "+f"(c[1]), "+f"(c[2]), "+f"(c[3])
        : "r"(a0), "r"(a1), "r"(a2), "r"(a3), "r"(b0), "r"(b1));
}

// online-softmax pair combine
__device__ __forceinline__ void lse_combine(float& m, float& s, float m2, float s2) {
    float mx = fmaxf(m, m2);
    s = s * exp2f((m - mx) * L2E) + s2 * exp2f((m2 - mx) * L2E);
    m = mx;
}

// ---------------- K1: index build ----------------
__global__ void k_build(const int* __restrict__ bs, const int* __restrict__ sent, int T, int total) {
    __shared__ int off[257];
    int tid = threadIdx.x;
    if (tid == 0) {
        int acc = 0;
        for (int t = 0; t < T; ++t) { off[t] = acc; acc += bs[t]; }
        off[T] = acc;
    }
    __syncthreads();
    int rb = 0;
    for (int t = 1; t < T; ++t) {              // forward: h[t-1] predicts tok[t]
        int n = bs[t];
        for (int j = tid; j < n; j += blockDim.x) {
            g_ctx[rb + j] = off[t - 1] + j;
            g_tok[rb + j] = sent[off[t] + j];
        }
        rb += n;
    }
    int Nf = rb;
    for (int i = 1; i < T - 1; ++i) {          // backward: h[i+1] predicts tok[i]
        int n = bs[i + 1];
        for (int j = tid; j < n; j += blockDim.x) {
            g_ctx[rb + j] = off[i + 1] + j;
            g_tok[rb + j] = sent[off[i] + j];
        }
        rb += n;
    }
    int M = rb;
    for (int r = M + tid; r < MP; r += blockDim.x) { g_ctx[r] = 0; g_tok[r] = 0; }
    if (tid == 0) {
        g_hdr[0] = Nf; g_hdr[1] = M - Nf; g_hdr[2] = M;
        g_denom = (float)(2 * total - bs[0] - bs[T - 1]);
    }
}

// ---------------- K2: gather ctx rows -> bf16 A (zero pad rows) ----------------
__global__ void k_gather(const float* __restrict__ hid) {
    int row = blockIdx.x, tid = threadIdx.x;
    int M = g_hdr[2], Nf = g_hdr[0];
    uint2* dst = reinterpret_cast<uint2*>(&g_A[(size_t)row * DIMK]);
    if (row < M) {
        int src = g_ctx[row];
        const float4* p = reinterpret_cast<const float4*>(
            hid + (size_t)src * 2 * DIMK + (row < Nf ? 0 : DIMK));
        float4 v = p[tid];
        __nv_bfloat162 lo = __floats2bfloat162_rn(v.x, v.y);
        __nv_bfloat162 hi = __floats2bfloat162_rn(v.z, v.w);
        uint2 o;
        o.x = *reinterpret_cast<uint32_t*>(&lo);
        o.y = *reinterpret_cast<uint32_t*>(&hi);
        dst[tid] = o;
    } else {
        dst[tid] = make_uint2(0u, 0u);
    }
}

// ---------------- K3: weight fp32 -> bf16 ----------------
__global__ void k_wconv(const float* __restrict__ W) {
    const int n4 = VOCABN * DIMK / 4;
    for (int i = blockIdx.x * blockDim.x + threadIdx.x; i < n4; i += gridDim.x * blockDim.x) {
        float4 v = reinterpret_cast<const float4*>(W)[i];
        __nv_bfloat162 lo = __floats2bfloat162_rn(v.x, v.y);
        __nv_bfloat162 hi = __floats2bfloat162_rn(v.z, v.w);
        uint2 o;
        o.x = *reinterpret_cast<uint32_t*>(&lo);
        o.y = *reinterpret_cast<uint32_t*>(&hi);
        reinterpret_cast<uint2*>(g_W)[i] = o;
    }
}

// ---------------- K4: mma.sync GEMM + fused softmax-partial epilogue ----------------
// grid = (NCH, MP/128), 256 threads (8 warps as 4(M) x 2(N)).
// CTA tile 128(M) x 128(N) x 64(K); warp tile 32(M) x 64(N).
// 3-stage cp.async pipeline, ONE __syncthreads per K-chunk.
// All cp.async addressing hoisted: per-chunk cost = 1 IADD per load.
#define GEMM_SMEM 102400
__global__ __launch_bounds__(256, 2)
void k_gemm(const float* __restrict__ fbias, const float* __restrict__ bbias) {
    extern __shared__ char dynsmem[];
    uint32_t raw = smem_u32(dynsmem);
    uint32_t pad = (1024u - (raw & 1023u)) & 1023u;
    uint32_t sb  = raw + pad;
    char* base   = dynsmem + pad;

    const uint32_t sA[3] = { sb,          sb + 16384, sb + 32768 };
    const uint32_t sB[3] = { sb + 49152,  sb + 65536, sb + 81920 };
    float*  biasF = reinterpret_cast<float*>(base + 98304);          // 128 f
    float*  biasB = biasF + 128;                                     // 128 f
    float2* scr   = reinterpret_cast<float2*>(base + 99328);         // [128][2]

    int tid  = threadIdx.x;
    int warp = tid >> 5;
    int lane = tid & 31;
    int wm   = warp >> 1;        // 0..3  (M strip of 32)
    int wn   = warp & 1;         // 0..1  (N strip of 64)
    int nb = blockIdx.x, mb = blockIdx.y;
    int n0 = nb * 128, m0 = mb * 128;

    if (tid < 128) biasF[tid] = fbias[n0 + tid];
    else           biasB[tid - 128] = bbias[n0 + tid - 128];

    // ---- hoisted cp.async addressing: per-thread smem offsets + running gmem ptrs ----
    uint32_t soff[4];
    const __nv_bfloat16* aP[4];
    const __nv_bfloat16* bP[4];
    {
        const __nv_bfloat16* Ag = g_A + (size_t)m0 * DIMK;
        const __nv_bfloat16* Bg = g_W + (size_t)n0 * DIMK;
        #pragma unroll
        for (int i = 0; i < 4; ++i) {
            int idx = tid + i * 256;
            int r = idx >> 3, c = idx & 7;
            uint32_t off = (uint32_t)(r * 128 + c * 16);
            soff[i] = off ^ ((off >> 3) & 0x70u);
            aP[i] = Ag + (size_t)r * DIMK + c * 8;
            bP[i] = Bg + (size_t)r * DIMK + c * 8;
        }
    }
    // issue one chunk (A+B) from current pointers into stage st, then advance by 64
    auto load_chunk = [&](int st) {
        uint32_t da = sA[st], db = sB[st];
        #pragma unroll
        for (int i = 0; i < 4; ++i) cp_async16(da + soff[i], aP[i]);
        #pragma unroll
        for (int i = 0; i < 4; ++i) cp_async16(db + soff[i], bP[i]);
        #pragma unroll
        for (int i = 0; i < 4; ++i) { aP[i] += 64; bP[i] += 64; }
    };

    // prologue: stages 0,1 in flight (group g <-> K-chunk g)
    load_chunk(0); cp_commit();
    load_chunk(1); cp_commit();

    float c[2][8][4];
    #pragma unroll
    for (int mi = 0; mi < 2; ++mi)
        #pragma unroll
        for (int nj = 0; nj < 8; ++nj)
            #pragma unroll
            for (int q = 0; q < 4; ++q) c[mi][nj][q] = 0.f;

    // fragment geometry (constant across chunks)
    const uint32_t a_row = (uint32_t)(wm * 32 + (lane & 15));        // + mi*16
    const uint32_t a_kb  = (uint32_t)((lane >> 4) << 4);             // 0 or 16 bytes
    const uint32_t b_row = (uint32_t)(wn * 64 + (lane & 7) + ((lane >> 4) << 3)); // + nj2*16
    const uint32_t b_kb  = (uint32_t)(((lane >> 3) & 1) << 4);       // 0 or 16 bytes
    // swizzle hoist: for 128B rows, XOR mask = (row & 7) << 4 (depends only on row)
    const uint32_t km_a  = a_kb ^ ((a_row & 7u) << 4);
    const uint32_t km_b  = b_kb ^ ((b_row & 7u) << 4);
    const uint32_t a_ro[2] = { a_row * 128u, (a_row + 16u) * 128u };
    const uint32_t b_ro[4] = { b_row * 128u, (b_row + 16u) * 128u,
                               (b_row + 32u) * 128u, (b_row + 48u) * 128u };

    int stage = 0;
    for (int kc = 0; kc < KCH; ++kc) {
        cp_wait1();        // stage kc resident
        __syncthreads();   // stage (kc-1) fully consumed -> refillable

        // issue next global load FIRST so LSU overlaps the MMA block below
        int nstage = stage + 2; if (nstage >= 3) nstage -= 3;
        if (kc + 2 < KCH) load_chunk(nstage);
        cp_commit();       // uniform group accounting (empty groups ok)

        const uint32_t aAd0 = sA[stage] + a_ro[0], aAd1 = sA[stage] + a_ro[1];
        const uint32_t bAd0 = sB[stage] + b_ro[0], bAd1 = sB[stage] + b_ro[1];
        const uint32_t bAd2 = sB[stage] + b_ro[2], bAd3 = sB[stage] + b_ro[3];

        uint32_t af[2][2][4];   // [buf][mi][reg]
        uint32_t bf[2][4][4];   // [buf][nj2][reg]

        // load s=0 fragments into buf 0
        {
            uint32_t ta = km_a, tb = km_b;
            ldmatrix_x4(af[0][0][0], af[0][0][1], af[0][0][2], af[0][0][3], aAd0 + ta);
            ldmatrix_x4(af[0][1][0], af[0][1][1], af[0][1][2], af[0][1][3], aAd1 + ta);
            ldmatrix_x4(bf[0][0][0], bf[0][0][1], bf[0][0][2], bf[0][0][3], bAd0 + tb);
            ldmatrix_x4(bf[0][1][0], bf[0][1][1], bf[0][1][2], bf[0][1][3], bAd1 + tb);
            ldmatrix_x4(bf[0][2][0], bf[0][2][1], bf[0][2][2], bf[0][2][3], bAd2 + tb);
            ldmatrix_x4(bf[0][3][0], bf[0][3][1], bf[0][3][2], bf[0][3][3], bAd3 + tb);
        }
        #pragma unroll
        for (int s = 0; s < 4; ++s) {
            int cur = s & 1, nxt = cur ^ 1;
            if (s < 3) {   // prefetch fragments for s+1 while MMAs below run
                uint32_t ta = ((uint32_t)(s + 1) * 32u) ^ km_a;
                uint32_t tb = ((uint32_t)(s + 1) * 32u) ^ km_b;
                ldmatrix_x4(af[nxt][0][0], af[nxt][0][1], af[nxt][0][2], af[nxt][0][3], aAd0 + ta);
                ldmatrix_x4(af[nxt][1][0], af[nxt][1][1], af[nxt][1][2], af[nxt][1][3], aAd1 + ta);
                ldmatrix_x4(bf[nxt][0][0], bf[nxt][0][1], bf[nxt][0][2], bf[nxt][0][3], bAd0 + tb);
                ldmatrix_x4(bf[nxt][1][0], bf[nxt][1][1], bf[nxt][1][2], bf[nxt][1][3], bAd1 + tb);
                ldmatrix_x4(bf[nxt][2][0], bf[nxt][2][1], bf[nxt][2][2], bf[nxt][2][3], bAd2 + tb);
                ldmatrix_x4(bf[nxt][3][0], bf[nxt][3][1], bf[nxt][3][2], bf[nxt][3][3], bAd3 + tb);
            }
            #pragma unroll
            for (int nj2 = 0; nj2 < 4; ++nj2) {
                #pragma unroll
                for (int mi = 0; mi < 2; ++mi) {
                    mma16816(c[mi][2 * nj2],
                             af[cur][mi][0], af[cur][mi][1], af[cur][mi][2], af[cur][mi][3],
                             bf[cur][nj2][0], bf[cur][nj2][1]);
                    mma16816(c[mi][2 * nj2 + 1],
                             af[cur][mi][0], af[cur][mi][1], af[cur][mi][2], af[cur][mi][3],
                             bf[cur][nj2][2], bf[cur][nj2][3]);
                }
            }
        }
        ++stage; if (stage == 3) stage = 0;
    }

    // ----- epilogue: branch-free two-pass per-row max / exp-sum over 64 cols -----
    int Nf = g_hdr[0];
    int cb = wn * 64 + (lane & 3) * 2;      // local col of c[.][nj][0]
    const float* bp[2][2];
    int lrow[2][2];
    float mx[2][2], sm[2][2];
    #pragma unroll
    for (int mi = 0; mi < 2; ++mi)
        #pragma unroll
        for (int h = 0; h < 2; ++h) {
            lrow[mi][h] = wm * 32 + mi * 16 + h * 8 + (lane >> 2);
            bp[mi][h]   = (m0 + lrow[mi][h] < Nf) ? biasF : biasB;
            mx[mi][h]   = -3.4e38f;
            sm[mi][h]   = 0.f;
        }
    // pass 1: add bias in place, track per-lane max
    #pragma unroll
    for (int nj = 0; nj < 8; ++nj) {
        int col = cb + nj * 8;
        #pragma unroll
        for (int mi = 0; mi < 2; ++mi) {
            c[mi][nj][0] += bp[mi][0][col];
            c[mi][nj][1] += bp[mi][0][col + 1];
            c[mi][nj][2] += bp[mi][1][col];
            c[mi][nj][3] += bp[mi][1][col + 1];
            mx[mi][0] = fmaxf(mx[mi][0], fmaxf(c[mi][nj][0], c[mi][nj][1]));
            mx[mi][1] = fmaxf(mx[mi][1], fmaxf(c[mi][nj][2], c[mi][nj][3]));
        }
    }
    // quad max (lanes differing in bits 0,1 share each row)
    #pragma unroll
    for (int mi = 0; mi < 2; ++mi)
        #pragma unroll
        for (int h = 0; h < 2; ++h) {
            mx[mi][h] = fmaxf(mx[mi][h], __shfl_xor_sync(0xffffffffu, mx[mi][h], 1));
            mx[mi][h] = fmaxf(mx[mi][h], __shfl_xor_sync(0xffffffffu, mx[mi][h], 2));
        }
    // pass 2: exp-sum with shared row max
    #pragma unroll
    for (int nj = 0; nj < 8; ++nj) {
        #pragma unroll
        for (int mi = 0; mi < 2; ++mi) {
            sm[mi][0] += exp2f((c[mi][nj][0] - mx[mi][0]) * L2E)
                       + exp2f((c[mi][nj][1] - mx[mi][0]) * L2E);
            sm[mi][1] += exp2f((c[mi][nj][2] - mx[mi][1]) * L2E)
                       + exp2f((c[mi][nj][3] - mx[mi][1]) * L2E);
        }
    }
    #pragma unroll
    for (int mi = 0; mi < 2; ++mi)
        #pragma unroll
        for (int h = 0; h < 2; ++h) {
            sm[mi][h] += __shfl_xor_sync(0xffffffffu, sm[mi][h], 1);
            sm[mi][h] += __shfl_xor_sync(0xffffffffu, sm[mi][h], 2);
        }
    if ((lane & 3) == 0) {
        #pragma unroll
        for (int mi = 0; mi < 2; ++mi)
            #pragma unroll
            for (int h = 0; h < 2; ++h)
                scr[lrow[mi][h] * 2 + wn] = make_float2(mx[mi][h], sm[mi][h]);
    }
    __syncthreads();
    if (tid < 128) {
        float2 p0 = scr[tid * 2 + 0], p1 = scr[tid * 2 + 1];
        lse_combine(p0.x, p0.y, p1.x, p1.y);
        g_part[(size_t)(m0 + tid) * NCH + nb] = p0;
    }
}

// ---------------- K5: per-row lse reduce over 250 partials + exact gold logit ----------------
__global__ void k_lsegold(const float* __restrict__ hid, const float* __restrict__ W,
                          const float* __restrict__ fb, const float* __restrict__ bb) {
    __shared__ float red[256];
    int row = blockIdx.x, tid = threadIdx.x;
    int M = g_hdr[2], Nf = g_hdr[0];

    // --- lse over 250 partials ---
    float2 p = (tid < NCH) ? g_part[(size_t)row * NCH + tid] : make_float2(-3.4e38f, 0.f);
    red[tid] = p.x; __syncthreads();
    for (int s = 128; s > 0; s >>= 1) {
        if (tid < s) red[tid] = fmaxf(red[tid], red[tid + s]);
        __syncthreads();
    }
    float gmax = red[0]; __syncthreads();
    red[tid] = p.y * exp2f((p.x - gmax) * L2E);
    __syncthreads();
    for (int s = 128; s > 0; s >>= 1) {
        if (tid < s) red[tid] += red[tid + s];
        __syncthreads();
    }
    if (tid == 0) g_lse[row] = gmax + LN2 * log2f(red[0]);

    // --- exact fp32 gold logit ---
    if (row >= M) return;
    int src = g_ctx[row], tok = g_tok[row];
    const float4* h4 = reinterpret_cast<const float4*>(
        hid + (size_t)src * 2 * DIMK + (row < Nf ? 0 : DIMK));
    const float4* w4 = reinterpret_cast<const float4*>(W + (size_t)tok * DIMK);
    float4 a = h4[tid], b = w4[tid];
    __syncthreads();
    red[tid] = a.x * b.x + a.y * b.y + a.z * b.z + a.w * b.w;
    __syncthreads();
    for (int s = 128; s > 0; s >>= 1) {
        if (tid < s) red[tid] += red[tid + s];
        __syncthreads();
    }
    if (tid == 0) g_gold[row] = red[0] + (row < Nf ? fb[tok] : bb[tok]);
}

// ---------------- K7: final scalar ----------------
__global__ void k_final(float* __restrict__ out) {
    __shared__ float red[1024];
    int tid = threadIdx.x, M = g_hdr[2];
    float a = 0.f;
    for (int r = tid; r < M; r += 1024) a += g_lse[r] - g_gold[r];
    red[tid] = a; __syncthreads();
    for (int s = 512; s > 0; s >>= 1) {
        if (tid < s) red[tid] += red[tid + s];
        __syncthreads();
    }
    if (tid == 0) out[0] = red[0] / g_denom;
}

// ---------------- launch ----------------
extern "C" void kernel_launch(void* const* d_in, const int* in_sizes, int n_in,
                              void* d_out, int out_size) {
    const float* hid  = (const float*)d_in[0];
    const float* W    = (const float*)d_in[1];
    const float* fb   = (const float*)d_in[2];
    const float* bb   = (const float*)d_in[3];
    const int*   sent = (const int*)d_in[4];
    const int*   bs   = (const int*)d_in[5];
    int total = in_sizes[4];
    int T     = in_sizes[5];

    cudaFuncSetAttribute(k_gemm, cudaFuncAttributeMaxDynamicSharedMemorySize, GEMM_SMEM);

    k_build<<<1, 256>>>(bs, sent, T, total);
    k_gather<<<MP, 256>>>(hid);
    k_wconv<<<4096, 256>>>(W);
    k_gemm<<<dim3(NCH, MP / 128), 256, GEMM_SMEM>>>(fb, bb);
    k_lsegold<<<MP, 256>>>(hid, W, fb, bb);
    k_final<<<1, 1024>>>((float*)d_out);
}